// round 5
// baseline (speedup 1.0000x reference)
#include <cuda_runtime.h>
#include <cuda_bf16.h>

#define NUM_CLASSES 1000
#define FEAT_DIM    512
#define BATCH       65536
#define BANKS       16
#define TPB         512   // 16 warps per block
#define GRID        (BATCH / (TPB / 32))   // 4096 blocks, 1 sample per warp

// scratch (no allocations allowed) — zero-initialized at module load;
// the kernel re-zeroes them itself each invocation (self-cleaning).
__device__ float    g_sums[NUM_CLASSES * BANKS];
__device__ int      g_cnts[NUM_CLASSES * BANKS];
__device__ unsigned g_ticket;

__global__ __launch_bounds__(TPB) void fused_kernel(
    const float4* __restrict__ feat,
    const float4* __restrict__ cent,
    const long long* __restrict__ labels,
    float* __restrict__ out)
{
    const int tid    = blockIdx.x * TPB + threadIdx.x;
    const int sample = tid >> 5;
    const int lane   = threadIdx.x & 31;
    const int bank   = blockIdx.x & (BANKS - 1);

    const int lbl = (int)labels[sample];   // broadcast (all lanes same addr)

    const float4* fr = feat + (size_t)sample * (FEAT_DIM / 4);
    const float4* cr = cent + (size_t)lbl    * (FEAT_DIM / 4);

    float acc = 0.0f;
#pragma unroll
    for (int k = 0; k < 4; k++) {
        float4 a = fr[lane + 32 * k];
        float4 b = cr[lane + 32 * k];
        float dx = a.x - b.x;
        float dy = a.y - b.y;
        float dz = a.z - b.z;
        float dw = a.w - b.w;
        acc = fmaf(dx, dx, acc);
        acc = fmaf(dy, dy, acc);
        acc = fmaf(dz, dz, acc);
        acc = fmaf(dw, dw, acc);
    }

#pragma unroll
    for (int off = 16; off > 0; off >>= 1)
        acc += __shfl_xor_sync(0xFFFFFFFFu, acc, off);

    if (lane == 0) {
        atomicAdd(&g_sums[lbl * BANKS + bank], acc);
        atomicAdd(&g_cnts[lbl * BANKS + bank], 1);
    }

    // ---- last-block finalize (threadfence-reduction pattern) ----
    __shared__ bool s_last;
    __syncthreads();                 // block's atomics are program-order before this
    if (threadIdx.x == 0) {
        __threadfence();             // make this block's updates device-visible
        unsigned t = atomicAdd(&g_ticket, 1);
        s_last = (t == (unsigned)(gridDim.x - 1));
    }
    __syncthreads();
    if (!s_last) return;

    // Only the last block runs here; all other blocks' atomics are L2-visible.
    float v = 0.0f;
    for (int j = threadIdx.x; j < NUM_CLASSES; j += TPB) {
        float s = 0.0f;
        int   c = 0;
#pragma unroll
        for (int b = 0; b < BANKS; b++) {
            s += __ldcg(&g_sums[j * BANKS + b]);   // L2 load, bypass L1
            c += __ldcg(&g_cnts[j * BANKS + b]);
        }
        if (c > 0)
            v += s / ((float)c * (float)FEAT_DIM * (float)BATCH);
        // re-zero for the next invocation (self-cleaning)
#pragma unroll
        for (int b = 0; b < BANKS; b++) {
            g_sums[j * BANKS + b] = 0.0f;
            g_cnts[j * BANKS + b] = 0;
        }
    }

    // block reduce (TPB = 512 -> 16 warps)
#pragma unroll
    for (int off = 16; off > 0; off >>= 1)
        v += __shfl_xor_sync(0xFFFFFFFFu, v, off);

    __shared__ float sh[TPB / 32];
    if ((threadIdx.x & 31) == 0) sh[threadIdx.x >> 5] = v;
    __syncthreads();

    if (threadIdx.x < 32) {
        float t = (threadIdx.x < TPB / 32) ? sh[threadIdx.x] : 0.0f;
#pragma unroll
        for (int off = 16; off > 0; off >>= 1)
            t += __shfl_xor_sync(0xFFFFFFFFu, t, off);
        if (threadIdx.x == 0) {
            out[0]   = t;
            g_ticket = 0;            // reset for next invocation
        }
    }
}

extern "C" void kernel_launch(void* const* d_in, const int* in_sizes, int n_in,
                              void* d_out, int out_size) {
    const float4*    feat   = (const float4*)d_in[0];
    const float4*    cent   = (const float4*)d_in[1];
    const long long* labels = (const long long*)d_in[2];
    float* out = (float*)d_out;

    fused_kernel<<<GRID, TPB>>>(feat, cent, labels, out);
}

// round 6
// speedup vs baseline: 1.3878x; 1.3878x over previous
#include <cuda_runtime.h>
#include <cuda_bf16.h>

#define NUM_CLASSES 1000
#define FEAT_DIM    512
#define BATCH       65536

// scratch — zero-initialized at module load; kernel2's last block re-zeroes
// them each invocation (self-cleaning, graph-replay safe).
__device__ int      g_cnts[NUM_CLASSES];
__device__ unsigned g_ticket;

// Launch 1: zero the output scalar + count labels (int atomics, cheap).
__global__ __launch_bounds__(1024) void count_kernel(
    const long long* __restrict__ labels, float* __restrict__ out)
{
    int i = blockIdx.x * 1024 + threadIdx.x;
    if (i == 0) out[0] = 0.0f;
    if (i < BATCH)
        atomicAdd(&g_cnts[(int)labels[i]], 1);
}

// Launch 2: R1's measured-fast structure — one warp per sample, 8 warps/block,
// plain float4 loads, warp shuffle reduce, ONE single-address atomic per block.
__global__ __launch_bounds__(256) void dist_kernel(
    const float4* __restrict__ feat,
    const float4* __restrict__ cent,
    const long long* __restrict__ labels,
    float* __restrict__ out)
{
    const int tid    = blockIdx.x * 256 + threadIdx.x;
    const int sample = tid >> 5;
    const int lane   = threadIdx.x & 31;
    const int wid    = threadIdx.x >> 5;

    const int lbl = (int)labels[sample];   // broadcast load (all lanes same addr)

    const float4* fr = feat + (size_t)sample * (FEAT_DIM / 4);
    const float4* cr = cent + (size_t)lbl    * (FEAT_DIM / 4);

    float acc = 0.0f;
#pragma unroll
    for (int k = 0; k < 4; k++) {
        float4 a = fr[lane + 32 * k];
        float4 b = cr[lane + 32 * k];
        float dx = a.x - b.x;
        float dy = a.y - b.y;
        float dz = a.z - b.z;
        float dw = a.w - b.w;
        acc = fmaf(dx, dx, acc);
        acc = fmaf(dy, dy, acc);
        acc = fmaf(dz, dz, acc);
        acc = fmaf(dw, dw, acc);
    }

    // warp reduce
#pragma unroll
    for (int off = 16; off > 0; off >>= 1)
        acc += __shfl_xor_sync(0xFFFFFFFFu, acc, off);

    __shared__ float s[8];
    if (lane == 0) {
        // this sample's own label => count >= 1, no zero-guard needed
        int   c = g_cnts[lbl];               // 1000 hot ints, cache-resident
        float w = 1.0f / ((float)c * ((float)FEAT_DIM * (float)BATCH));
        s[wid] = acc * w;
    }
    __syncthreads();

    if (threadIdx.x == 0) {
        float t = 0.0f;
#pragma unroll
        for (int w = 0; w < 8; w++) t += s[w];
        atomicAdd(out, t);                   // single address, 8192 total
    }

    // ---- self-cleaning tail: last block re-zeroes counts + ticket ----
    __shared__ bool s_last;
    if (threadIdx.x == 0) {
        __threadfence();
        unsigned t = atomicAdd(&g_ticket, 1);
        s_last = (t == (unsigned)(gridDim.x - 1));
    }
    __syncthreads();
    if (!s_last) return;

    for (int j = threadIdx.x; j < NUM_CLASSES; j += 256)
        g_cnts[j] = 0;
    if (threadIdx.x == 0)
        g_ticket = 0;
}

extern "C" void kernel_launch(void* const* d_in, const int* in_sizes, int n_in,
                              void* d_out, int out_size) {
    const float4*    feat   = (const float4*)d_in[0];
    const float4*    cent   = (const float4*)d_in[1];
    const long long* labels = (const long long*)d_in[2];
    float* out = (float*)d_out;

    count_kernel<<<BATCH / 1024, 1024>>>(labels, out);
    dist_kernel<<<BATCH / 8, 256>>>(feat, cent, labels, out);
}

// round 8
// speedup vs baseline: 2.2705x; 1.6361x over previous
#include <cuda_runtime.h>
#include <cuda_bf16.h>

#define NUM_CLASSES 1000
#define FEAT_DIM    512
#define BATCH       65536

// scratch — zero-initialized at module load; dist's last block re-zeroes
// them each invocation (self-cleaning, graph-replay safe).
__device__ int      g_cnts[NUM_CLASSES];
__device__ unsigned g_ticket;

// Launch 1: smem-histogram label count (16 blocks x 1024 thr x 4 labels).
// Global atomic contention per class drops 65 -> <=16.
__global__ __launch_bounds__(1024) void count_kernel(
    const long long* __restrict__ labels, float* __restrict__ out)
{
    __shared__ int h[NUM_CLASSES];
    for (int j = threadIdx.x; j < NUM_CLASSES; j += 1024)
        h[j] = 0;
    if (blockIdx.x == 0 && threadIdx.x == 0)
        out[0] = 0.0f;
    __syncthreads();

    const int base = blockIdx.x * 4096;
#pragma unroll
    for (int k = 0; k < 4; k++) {
        int l = (int)labels[base + k * 1024 + threadIdx.x];
        atomicAdd_block(&h[l], 1);
    }
    __syncthreads();

    for (int j = threadIdx.x; j < NUM_CLASSES; j += 1024) {
        int c = h[j];
        if (c) atomicAdd(&g_cnts[j], c);
    }
}

// Launch 2: R1's measured-fast hot loop. One warp per sample, 8 warps/block,
// plain float4 loads, warp shuffle reduce, ONE single-address RED per block.
// Self-cleaning tail uses an acq_rel ticket atomic — NO __threadfence, so no
// CCTL.IVALL L1-flush storm (the R6 regression).
__global__ __launch_bounds__(256) void dist_kernel(
    const float4* __restrict__ feat,
    const float4* __restrict__ cent,
    const long long* __restrict__ labels,
    float* __restrict__ out)
{
    const int tid    = blockIdx.x * 256 + threadIdx.x;
    const int sample = tid >> 5;
    const int lane   = threadIdx.x & 31;
    const int wid    = threadIdx.x >> 5;

    const int lbl = (int)labels[sample];   // broadcast load (all lanes same addr)

    const float4* fr = feat + (size_t)sample * (FEAT_DIM / 4);
    const float4* cr = cent + (size_t)lbl    * (FEAT_DIM / 4);

    float acc = 0.0f;
#pragma unroll
    for (int k = 0; k < 4; k++) {
        float4 a = fr[lane + 32 * k];
        float4 b = cr[lane + 32 * k];
        float dx = a.x - b.x;
        float dy = a.y - b.y;
        float dz = a.z - b.z;
        float dw = a.w - b.w;
        acc = fmaf(dx, dx, acc);
        acc = fmaf(dy, dy, acc);
        acc = fmaf(dz, dz, acc);
        acc = fmaf(dw, dw, acc);
    }

    // warp reduce
#pragma unroll
    for (int off = 16; off > 0; off >>= 1)
        acc += __shfl_xor_sync(0xFFFFFFFFu, acc, off);

    __shared__ float s[8];
    if (lane == 0) {
        int   c = g_cnts[lbl];               // 1000 hot ints, cache-resident
        float w = 1.0f / ((float)c * ((float)FEAT_DIM * (float)BATCH));
        s[wid] = acc * w;
    }
    __syncthreads();

    if (threadIdx.x == 0) {
        float t = 0.0f;
#pragma unroll
        for (int w = 0; w < 8; w++) t += s[w];
        atomicAdd(out, t);                   // single address, 8192 total
    }

    // ---- self-cleaning tail: acq_rel ticket, no L1-flushing fence ----
    __shared__ bool s_last;
    if (threadIdx.x == 0) {
        unsigned t;
        asm volatile("atom.global.add.acq_rel.gpu.u32 %0, [%1], 1;"
                     : "=r"(t) : "l"(&g_ticket) : "memory");
        s_last = (t == (unsigned)(gridDim.x - 1));
    }
    __syncthreads();
    if (!s_last) return;

    // last block: all other blocks have finished reading g_cnts (release-ordered
    // before their ticket add); safe to zero for the next replay.
    for (int j = threadIdx.x; j < NUM_CLASSES; j += 256)
        g_cnts[j] = 0;
    if (threadIdx.x == 0)
        g_ticket = 0;
}

extern "C" void kernel_launch(void* const* d_in, const int* in_sizes, int n_in,
                              void* d_out, int out_size) {
    const float4*    feat   = (const float4*)d_in[0];
    const float4*    cent   = (const float4*)d_in[1];
    const long long* labels = (const long long*)d_in[2];
    float* out = (float*)d_out;

    count_kernel<<<16, 1024>>>(labels, out);
    dist_kernel<<<BATCH / 8, 256>>>(feat, cent, labels, out);
}

// round 11
// speedup vs baseline: 2.9079x; 1.2807x over previous
#include <cuda_runtime.h>
#include <cuda_bf16.h>

#define NUM_CLASSES 1000
#define FEAT_DIM    512
#define BATCH       65536
#define NBLK        16      // count-kernel blocks / partial histograms

// Partial histograms, transposed: g_part[j*NBLK + b] = count of class j in block b.
// Fully overwritten by every invocation (plain stores) -> no cross-call state,
// no cleanup, no fences anywhere. 64 KB, L1-resident during dist.
__device__ int g_part[NUM_CLASSES * NBLK];

// Launch 1: per-block smem histogram, plain-stored to g_part. ZERO global atomics.
__global__ __launch_bounds__(1024) void count_kernel(
    const long long* __restrict__ labels, float* __restrict__ out)
{
    __shared__ int h[NUM_CLASSES];
    for (int j = threadIdx.x; j < NUM_CLASSES; j += 1024)
        h[j] = 0;
    if (blockIdx.x == 0 && threadIdx.x == 0)
        out[0] = 0.0f;
    __syncthreads();

    const int base = blockIdx.x * (BATCH / NBLK);
#pragma unroll
    for (int k = 0; k < BATCH / NBLK / 1024; k++) {
        int l = (int)labels[base + k * 1024 + threadIdx.x];
        atomicAdd_block(&h[l], 1);
    }
    __syncthreads();

    for (int j = threadIdx.x; j < NUM_CLASSES; j += 1024)
        g_part[j * NBLK + blockIdx.x] = h[j];
}

// Launch 2: R1's measured-fast hot loop, UNMODIFIED tail-free structure.
// One warp per sample, 8 warps/block, plain float4 loads, warp shuffle reduce,
// ONE single-address RED per block. Count gathered from 16 contiguous partials.
__global__ __launch_bounds__(256) void dist_kernel(
    const float4* __restrict__ feat,
    const float4* __restrict__ cent,
    const long long* __restrict__ labels,
    float* __restrict__ out)
{
    const int tid    = blockIdx.x * 256 + threadIdx.x;
    const int sample = tid >> 5;
    const int lane   = threadIdx.x & 31;
    const int wid    = threadIdx.x >> 5;

    const int lbl = (int)labels[sample];   // broadcast load (all lanes same addr)

    const float4* fr = feat + (size_t)sample * (FEAT_DIM / 4);
    const float4* cr = cent + (size_t)lbl    * (FEAT_DIM / 4);

    float acc = 0.0f;
#pragma unroll
    for (int k = 0; k < 4; k++) {
        float4 a = fr[lane + 32 * k];
        float4 b = cr[lane + 32 * k];
        float dx = a.x - b.x;
        float dy = a.y - b.y;
        float dz = a.z - b.z;
        float dw = a.w - b.w;
        acc = fmaf(dx, dx, acc);
        acc = fmaf(dy, dy, acc);
        acc = fmaf(dz, dz, acc);
        acc = fmaf(dw, dw, acc);
    }

    // gather this class's 16 count partials (64 B contiguous, L1-hot)
    int c = (lane < NBLK) ? g_part[lbl * NBLK + lane] : 0;

    // fused warp reduce: acc (all lanes) and c (16 lanes -> total)
#pragma unroll
    for (int off = 16; off > 0; off >>= 1) {
        acc += __shfl_xor_sync(0xFFFFFFFFu, acc, off);
        c   += __shfl_xor_sync(0xFFFFFFFFu, c,   off);
    }

    __shared__ float s[8];
    if (lane == 0) {
        float w = 1.0f / ((float)c * ((float)FEAT_DIM * (float)BATCH));
        s[wid] = acc * w;
    }
    __syncthreads();

    if (threadIdx.x == 0) {
        float t = 0.0f;
#pragma unroll
        for (int w = 0; w < 8; w++) t += s[w];
        atomicAdd(out, t);                   // single address, 8192 total
    }
    // no tail: nothing to clean, nothing to fence
}

extern "C" void kernel_launch(void* const* d_in, const int* in_sizes, int n_in,
                              void* d_out, int out_size) {
    const float4*    feat   = (const float4*)d_in[0];
    const float4*    cent   = (const float4*)d_in[1];
    const long long* labels = (const long long*)d_in[2];
    float* out = (float*)d_out;

    count_kernel<<<NBLK, 1024>>>(labels, out);
    dist_kernel<<<BATCH / 8, 256>>>(feat, cent, labels, out);
}

// round 14
// speedup vs baseline: 2.9565x; 1.0167x over previous
#include <cuda_runtime.h>
#include <cuda_bf16.h>

#define NUM_CLASSES 1000
#define FEAT_DIM    512
#define BATCH       65536
#define NBLK        16      // count-kernel blocks / partial histograms

// Partial histograms, transposed: g_part[j*NBLK + b] = count of class j in block b.
// Fully overwritten every invocation (plain stores) -> stateless, graph-safe,
// no fences anywhere (fences at .gpu scope flush L1D -> measured regression).
__device__ int g_part[NUM_CLASSES * NBLK];

// Launch 1: per-block smem histogram, plain-stored to g_part. ZERO global atomics.
__global__ __launch_bounds__(1024) void count_kernel(
    const long long* __restrict__ labels, float* __restrict__ out)
{
    __shared__ int h[NUM_CLASSES];
    for (int j = threadIdx.x; j < NUM_CLASSES; j += 1024)
        h[j] = 0;
    if (blockIdx.x == 0 && threadIdx.x == 0)
        out[0] = 0.0f;
    __syncthreads();

    const int base = blockIdx.x * (BATCH / NBLK);
#pragma unroll
    for (int k = 0; k < BATCH / NBLK / 1024; k++) {
        int l = (int)labels[base + k * 1024 + threadIdx.x];
        atomicAdd_block(&h[l], 1);
    }
    __syncthreads();

    for (int j = threadIdx.x; j < NUM_CLASSES; j += 1024)
        g_part[j * NBLK + blockIdx.x] = h[j];
}

// Launch 2: one warp per sample, 8 warps/block. All 8 float4 loads issued
// BEFORE any arithmetic (front-batched -> MLP ~8). __launch_bounds__(256,4)
// budgets 64 regs/thread while keeping 32 warps/SM (full RF = 4*256*64).
__global__ __launch_bounds__(256, 4) void dist_kernel(
    const float4* __restrict__ feat,
    const float4* __restrict__ cent,
    const long long* __restrict__ labels,
    float* __restrict__ out)
{
    const int tid    = blockIdx.x * 256 + threadIdx.x;
    const int sample = tid >> 5;
    const int lane   = threadIdx.x & 31;
    const int wid    = threadIdx.x >> 5;

    const int lbl = (int)labels[sample];   // broadcast load (all lanes same addr)

    const float4* fr = feat + (size_t)sample * (FEAT_DIM / 4);
    const float4* cr = cent + (size_t)lbl    * (FEAT_DIM / 4);

    // ---- issue ALL loads first: 8 independent 128B transactions in flight ----
    float4 a0 = fr[lane];
    float4 a1 = fr[lane + 32];
    float4 a2 = fr[lane + 64];
    float4 a3 = fr[lane + 96];
    float4 b0 = cr[lane];
    float4 b1 = cr[lane + 32];
    float4 b2 = cr[lane + 64];
    float4 b3 = cr[lane + 96];

    // gather this class's 16 count partials (64 B contiguous, L1-hot) — also
    // issued before the FMA chain so it overlaps.
    int c = (lane < NBLK) ? g_part[lbl * NBLK + lane] : 0;

    // ---- arithmetic ----
    float acc = 0.0f;
    float d;
    d = a0.x - b0.x; acc = fmaf(d, d, acc);
    d = a0.y - b0.y; acc = fmaf(d, d, acc);
    d = a0.z - b0.z; acc = fmaf(d, d, acc);
    d = a0.w - b0.w; acc = fmaf(d, d, acc);
    d = a1.x - b1.x; acc = fmaf(d, d, acc);
    d = a1.y - b1.y; acc = fmaf(d, d, acc);
    d = a1.z - b1.z; acc = fmaf(d, d, acc);
    d = a1.w - b1.w; acc = fmaf(d, d, acc);
    d = a2.x - b2.x; acc = fmaf(d, d, acc);
    d = a2.y - b2.y; acc = fmaf(d, d, acc);
    d = a2.z - b2.z; acc = fmaf(d, d, acc);
    d = a2.w - b2.w; acc = fmaf(d, d, acc);
    d = a3.x - b3.x; acc = fmaf(d, d, acc);
    d = a3.y - b3.y; acc = fmaf(d, d, acc);
    d = a3.z - b3.z; acc = fmaf(d, d, acc);
    d = a3.w - b3.w; acc = fmaf(d, d, acc);

    // fused warp reduce: acc (all lanes) and c (16 lanes -> total)
#pragma unroll
    for (int off = 16; off > 0; off >>= 1) {
        acc += __shfl_xor_sync(0xFFFFFFFFu, acc, off);
        c   += __shfl_xor_sync(0xFFFFFFFFu, c,   off);
    }

    __shared__ float s[8];
    if (lane == 0) {
        float w = 1.0f / ((float)c * ((float)FEAT_DIM * (float)BATCH));
        s[wid] = acc * w;
    }
    __syncthreads();

    if (threadIdx.x == 0) {
        float t = 0.0f;
#pragma unroll
        for (int w = 0; w < 8; w++) t += s[w];
        atomicAdd(out, t);                   // single address, 8192 total
    }
    // no tail: nothing to clean, nothing to fence
}

extern "C" void kernel_launch(void* const* d_in, const int* in_sizes, int n_in,
                              void* d_out, int out_size) {
    const float4*    feat   = (const float4*)d_in[0];
    const float4*    cent   = (const float4*)d_in[1];
    const long long* labels = (const long long*)d_in[2];
    float* out = (float*)d_out;

    count_kernel<<<NBLK, 1024>>>(labels, out);
    dist_kernel<<<BATCH / 8, 256>>>(feat, cent, labels, out);
}